// round 2
// baseline (speedup 1.0000x reference)
#include <cuda_runtime.h>
#include <math.h>

#define NN 500000
#define NE 4000000
#define TAB 2048

// Persistent device scratch (allocation-free rule: __device__ globals).
// Node row: 32 floats = 128B, one L2 line per node.
//   [0:8) u   [8:16) v   [16:26) xc   [26:32) pad
__device__ __align__(128) float g_node[NN * 32];   // 64MB
// Accumulator row: 32 floats = 128B. [0:10) mi  [16:26) mo
__device__ __align__(128) float g_mimo[NN * 32];   // 64MB
__device__ __align__(16)  float2 g_tab[TAB + 8];   // tanh LUT (value, central slope)
__device__ __align__(16)  int2 g_ei[NE];           // packed (row, col)  32MB

// ---------------- tanh via shared-memory lerp LUT ----------------
// domain [-8, 8], 2048 cells; max abs error ~6e-6 (tanh saturates past 8).
__device__ __forceinline__ float tanh_lut(float x, const float2* t) {
    float s = fmaf(x, 128.0f, 1024.0f);
    s = fminf(fmaxf(s, 0.0f), 2047.0f);
    float m = s + 12582912.0f;              // 1.5*2^23 round trick
    int i = __float_as_int(m) & 0x7FF;
    float f = s - (m - 12582912.0f);        // frac in [-0.5, 0.5]
    float2 e = t[i];
    return fmaf(f, e.y, e.x);
}

// ---------------- vectorized global reductions (sm_90+) ----------------
__device__ __forceinline__ void red4(float* p, float a, float b, float c, float d) {
    asm volatile("red.global.add.v4.f32 [%0], {%1, %2, %3, %4};"
                 :: "l"(p), "f"(a), "f"(b), "f"(c), "f"(d) : "memory");
}
__device__ __forceinline__ void red2(float* p, float a, float b) {
    asm volatile("red.global.add.v2.f32 [%0], {%1, %2};"
                 :: "l"(p), "f"(a), "f"(b) : "memory");
}

__global__ void k_tab() {
    int i = blockIdx.x * blockDim.x + threadIdx.x;
    if (i <= TAB) {
        const float h = 1.0f / 128.0f;
        float xi = -8.0f + (float)i * h;
        g_tab[i] = make_float2(tanhf(xi), 0.5f * (tanhf(xi + h) - tanhf(xi - h)));
    }
}

__global__ void k_pack(const int* __restrict__ ei) {
    int i = blockIdx.x * blockDim.x + threadIdx.x;
    if (i < NE) g_ei[i] = make_int2(ei[i], ei[NE + i]);
}

// u_j = sum_k xc_k * e1w[k][j] + e1b[j]   (rows 0..9  -> multiplies x[col])
// v_j = sum_k xc_k * e1w[10+k][j]         (rows 10..19 -> multiplies x[row])
__device__ __forceinline__ void store_node_row(int n, const float* xc,
                                               const float* s_e1w, const float* s_e1b) {
    float u[8], v[8];
#pragma unroll
    for (int j = 0; j < 8; j++) { u[j] = s_e1b[j]; v[j] = 0.0f; }
#pragma unroll
    for (int k = 0; k < 10; k++) {
        float xk = xc[k];
        float4 a0 = *(const float4*)(s_e1w + k * 8);
        float4 a1 = *(const float4*)(s_e1w + k * 8 + 4);
        float4 b0 = *(const float4*)(s_e1w + (10 + k) * 8);
        float4 b1 = *(const float4*)(s_e1w + (10 + k) * 8 + 4);
        u[0] = fmaf(xk, a0.x, u[0]); u[1] = fmaf(xk, a0.y, u[1]);
        u[2] = fmaf(xk, a0.z, u[2]); u[3] = fmaf(xk, a0.w, u[3]);
        u[4] = fmaf(xk, a1.x, u[4]); u[5] = fmaf(xk, a1.y, u[5]);
        u[6] = fmaf(xk, a1.z, u[6]); u[7] = fmaf(xk, a1.w, u[7]);
        v[0] = fmaf(xk, b0.x, v[0]); v[1] = fmaf(xk, b0.y, v[1]);
        v[2] = fmaf(xk, b0.z, v[2]); v[3] = fmaf(xk, b0.w, v[3]);
        v[4] = fmaf(xk, b1.x, v[4]); v[5] = fmaf(xk, b1.y, v[5]);
        v[6] = fmaf(xk, b1.z, v[6]); v[7] = fmaf(xk, b1.w, v[7]);
    }
    float4* o = (float4*)(g_node + (size_t)n * 32);
    o[0] = make_float4(u[0], u[1], u[2], u[3]);
    o[1] = make_float4(u[4], u[5], u[6], u[7]);
    o[2] = make_float4(v[0], v[1], v[2], v[3]);
    o[3] = make_float4(v[4], v[5], v[6], v[7]);
    o[4] = make_float4(xc[0], xc[1], xc[2], xc[3]);
    o[5] = make_float4(xc[4], xc[5], xc[6], xc[7]);
    o[6] = make_float4(xc[8], xc[9], 0.0f, 0.0f);
}

// ---------------- init: H = tanh(X@win + b); node row; zero mimo ----------------
__global__ void k_init(const float* __restrict__ x,
                       const float* __restrict__ win_w, const float* __restrict__ win_b,
                       const float* __restrict__ e1_w, const float* __restrict__ e1_b) {
    __shared__ __align__(16) float2 s_tab[TAB];
    __shared__ __align__(16) float s_w[192];
    int tid = threadIdx.x;
    for (int i = tid; i < TAB; i += blockDim.x) s_tab[i] = g_tab[i];
    if (tid < 16) s_w[tid] = win_w[tid];
    if (tid >= 16 && tid < 24) s_w[tid] = win_b[tid - 16];
    for (int i = tid; i < 160; i += blockDim.x) s_w[24 + i] = e1_w[i];
    if (tid < 8) s_w[184 + tid] = e1_b[tid];
    __syncthreads();

    int n = blockIdx.x * blockDim.x + tid;
    if (n >= NN) return;

    float2 X = ((const float2*)x)[n];
    float xc[10];
#pragma unroll
    for (int j = 0; j < 8; j++) {
        float a = fmaf(X.x, s_w[j], fmaf(X.y, s_w[8 + j], s_w[16 + j]));
        xc[j] = tanh_lut(a, s_tab);
    }
    xc[8] = X.x; xc[9] = X.y;

    float4* mrow = (float4*)(g_mimo + (size_t)n * 32);
    float4 z4 = make_float4(0, 0, 0, 0);
#pragma unroll
    for (int q = 0; q < 8; q++) mrow[q] = z4;

    store_node_row(n, xc, s_w + 24, s_w + 184);
}

// ---------------- edge pass: e = sigmoid(w2 . tanh(u[c]+v[r]) + b2) ----------------
// iters: mi[c] += x[r]*e ; mo[r] += x[c]*e   |   final: out[i] = e
template <bool FINAL>
__global__ void k_edge(const float* __restrict__ e2_w, const float* __restrict__ e2_b,
                       float* __restrict__ out) {
    __shared__ __align__(16) float2 s_tab[TAB];
    __shared__ float s_w2[12];
    int tid = threadIdx.x;
    for (int i = tid; i < TAB; i += blockDim.x) s_tab[i] = g_tab[i];
    if (tid < 8) s_w2[tid] = e2_w[tid];
    if (tid == 8) s_w2[8] = e2_b[0];
    __syncthreads();

    float w0 = s_w2[0], w1 = s_w2[1], w2 = s_w2[2], w3 = s_w2[3];
    float w4 = s_w2[4], w5 = s_w2[5], w6 = s_w2[6], w7 = s_w2[7];
    float b2 = s_w2[8];

    int stride = gridDim.x * blockDim.x;
    for (int i = blockIdx.x * blockDim.x + tid; i < NE; i += stride) {
        int2 rc = g_ei[i];
        size_t r = (size_t)rc.x, c = (size_t)rc.y;
        const float4* cp = (const float4*)(g_node + c * 32);
        const float4* rp = (const float4*)(g_node + r * 32);

        float4 u0 = cp[0], u1 = cp[1];        // u[c]
        float4 v0 = rp[2], v1 = rp[3];        // v[r]

        float z = b2;
        z = fmaf(tanh_lut(u0.x + v0.x, s_tab), w0, z);
        z = fmaf(tanh_lut(u0.y + v0.y, s_tab), w1, z);
        z = fmaf(tanh_lut(u0.z + v0.z, s_tab), w2, z);
        z = fmaf(tanh_lut(u0.w + v0.w, s_tab), w3, z);
        z = fmaf(tanh_lut(u1.x + v1.x, s_tab), w4, z);
        z = fmaf(tanh_lut(u1.y + v1.y, s_tab), w5, z);
        z = fmaf(tanh_lut(u1.z + v1.z, s_tab), w6, z);
        z = fmaf(tanh_lut(u1.w + v1.w, s_tab), w7, z);
        float e = fmaf(tanh_lut(0.5f * z, s_tab), 0.5f, 0.5f);  // sigmoid(z)

        if (FINAL) {
            out[i] = e;
        } else {
            float4 xr0 = rp[4], xr1 = rp[5];  // xc of row node
            float4 xr2 = rp[6];
            float4 xc0 = cp[4], xc1 = cp[5];  // xc of col node
            float4 xc2 = cp[6];

            float* mc = g_mimo + c * 32;       // mi[col]
            float* mr = g_mimo + r * 32 + 16;  // mo[row]
            red4(mc,     xr0.x * e, xr0.y * e, xr0.z * e, xr0.w * e);
            red4(mc + 4, xr1.x * e, xr1.y * e, xr1.z * e, xr1.w * e);
            red2(mc + 8, xr2.x * e, xr2.y * e);
            red4(mr,     xc0.x * e, xc0.y * e, xc0.z * e, xc0.w * e);
            red4(mr + 4, xc1.x * e, xc1.y * e, xc1.z * e, xc1.w * e);
            red2(mr + 8, xc2.x * e, xc2.y * e);
        }
    }
}

// ---------------- node pass: H = tanh(tanh([mi,mo,xcat]@n1+b1)@n2+b2) ----------------
// smem: [0:240) n1w, [240:248) n1b, [248:312) n2w, [312:320) n2b,
//       [320:480) e1w, [480:488) e1b
__global__ void k_node(const float* __restrict__ e1_w, const float* __restrict__ e1_b,
                       const float* __restrict__ n1_w, const float* __restrict__ n1_b,
                       const float* __restrict__ n2_w, const float* __restrict__ n2_b) {
    __shared__ __align__(16) float2 s_tab[TAB];
    __shared__ __align__(16) float s_w[488];
    int tid = threadIdx.x;
    for (int i = tid; i < TAB; i += blockDim.x) s_tab[i] = g_tab[i];
    for (int i = tid; i < 240; i += blockDim.x) s_w[i] = n1_w[i];
    if (tid < 8) s_w[240 + tid] = n1_b[tid];
    for (int i = tid; i < 64; i += blockDim.x) s_w[248 + i] = n2_w[i];
    if (tid < 8) s_w[312 + tid] = n2_b[tid];
    for (int i = tid; i < 160; i += blockDim.x) s_w[320 + i] = e1_w[i];
    if (tid < 8) s_w[480 + tid] = e1_b[tid];
    __syncthreads();

    int n = blockIdx.x * blockDim.x + tid;
    if (n >= NN) return;

    float4* mrow = (float4*)(g_mimo + (size_t)n * 32);
    float4 mi0 = mrow[0], mi1 = mrow[1], mi2 = mrow[2];
    float4 mo0 = mrow[4], mo1 = mrow[5], mo2 = mrow[6];

    // reset accumulators for next edge pass
    float4 z4 = make_float4(0, 0, 0, 0);
#pragma unroll
    for (int q = 0; q < 8; q++) mrow[q] = z4;

    float4* nrow = (float4*)(g_node + (size_t)n * 32);
    float4 x0 = nrow[4], x1 = nrow[5], x2 = nrow[6];

    float M[30];
    M[0]=mi0.x; M[1]=mi0.y; M[2]=mi0.z; M[3]=mi0.w;
    M[4]=mi1.x; M[5]=mi1.y; M[6]=mi1.z; M[7]=mi1.w;
    M[8]=mi2.x; M[9]=mi2.y;
    M[10]=mo0.x; M[11]=mo0.y; M[12]=mo0.z; M[13]=mo0.w;
    M[14]=mo1.x; M[15]=mo1.y; M[16]=mo1.z; M[17]=mo1.w;
    M[18]=mo2.x; M[19]=mo2.y;
    M[20]=x0.x; M[21]=x0.y; M[22]=x0.z; M[23]=x0.w;
    M[24]=x1.x; M[25]=x1.y; M[26]=x1.z; M[27]=x1.w;
    M[28]=x2.x; M[29]=x2.y;

    float a[8];
#pragma unroll
    for (int j = 0; j < 8; j++) a[j] = s_w[240 + j];
#pragma unroll
    for (int k = 0; k < 30; k++) {
        float mk = M[k];
        float4 wA = *(const float4*)(s_w + k * 8);
        float4 wB = *(const float4*)(s_w + k * 8 + 4);
        a[0] = fmaf(mk, wA.x, a[0]); a[1] = fmaf(mk, wA.y, a[1]);
        a[2] = fmaf(mk, wA.z, a[2]); a[3] = fmaf(mk, wA.w, a[3]);
        a[4] = fmaf(mk, wB.x, a[4]); a[5] = fmaf(mk, wB.y, a[5]);
        a[6] = fmaf(mk, wB.z, a[6]); a[7] = fmaf(mk, wB.w, a[7]);
    }
    float h[8];
#pragma unroll
    for (int j = 0; j < 8; j++) h[j] = tanh_lut(a[j], s_tab);

    float g[8];
#pragma unroll
    for (int j = 0; j < 8; j++) g[j] = s_w[312 + j];
#pragma unroll
    for (int k = 0; k < 8; k++) {
        float hk = h[k];
        float4 wA = *(const float4*)(s_w + 248 + k * 8);
        float4 wB = *(const float4*)(s_w + 248 + k * 8 + 4);
        g[0] = fmaf(hk, wA.x, g[0]); g[1] = fmaf(hk, wA.y, g[1]);
        g[2] = fmaf(hk, wA.z, g[2]); g[3] = fmaf(hk, wA.w, g[3]);
        g[4] = fmaf(hk, wB.x, g[4]); g[5] = fmaf(hk, wB.y, g[5]);
        g[6] = fmaf(hk, wB.z, g[6]); g[7] = fmaf(hk, wB.w, g[7]);
    }

    float xc[10];
#pragma unroll
    for (int j = 0; j < 8; j++) xc[j] = tanh_lut(g[j], s_tab);
    xc[8] = x2.x; xc[9] = x2.y;

    store_node_row(n, xc, s_w + 320, s_w + 480);
}

extern "C" void kernel_launch(void* const* d_in, const int* in_sizes, int n_in,
                              void* d_out, int out_size) {
    const float* x     = (const float*)d_in[0];
    const int*   ei    = (const int*)d_in[1];
    const float* win_w = (const float*)d_in[2];
    const float* win_b = (const float*)d_in[3];
    const float* e1_w  = (const float*)d_in[4];
    const float* e1_b  = (const float*)d_in[5];
    const float* e2_w  = (const float*)d_in[6];
    const float* e2_b  = (const float*)d_in[7];
    const float* n1_w  = (const float*)d_in[8];
    const float* n1_b  = (const float*)d_in[9];
    const float* n2_w  = (const float*)d_in[10];
    const float* n2_b  = (const float*)d_in[11];
    float* out = (float*)d_out;

    k_tab<<<9, 256>>>();
    k_pack<<<(NE + 255) / 256, 256>>>(ei);
    k_init<<<(NN + 255) / 256, 256>>>(x, win_w, win_b, e1_w, e1_b);
    for (int it = 0; it < 3; it++) {
        k_edge<false><<<2368, 256>>>(e2_w, e2_b, nullptr);
        k_node<<<(NN + 255) / 256, 256>>>(e1_w, e1_b, n1_w, n1_b, n2_w, n2_b);
    }
    k_edge<true><<<2368, 256>>>(e2_w, e2_b, out);
}

// round 3
// speedup vs baseline: 1.2539x; 1.2539x over previous
#include <cuda_runtime.h>
#include <cuda_fp16.h>
#include <math.h>

#define NN 500000
#define NE 4000000
#define TAB 2048

// Persistent device scratch (allocation-free rule: __device__ globals).
// Node row: 32 halves = 64B.  [0:8) u  [8:16) v  [16:26) xc  [26:32) pad
__device__ __align__(128) __half g_node[NN * 32];  // 32MB
// Accumulator row: 32 floats = 128B. [0:10) mi  [16:26) mo
__device__ __align__(128) float g_mimo[NN * 32];   // 64MB
__device__ __align__(16)  float2 g_tab[TAB + 8];   // tanh LUT (value, central slope)
__device__ __align__(16)  int2 g_ei[NE];           // packed (row, col)  32MB

// ---------------- tanh via shared-memory lerp LUT ----------------
// domain [-8, 8], 2048 cells; max abs error ~6e-6 (tanh saturates past 8).
__device__ __forceinline__ float tanh_lut(float x, const float2* t) {
    float s = fmaf(x, 128.0f, 1024.0f);
    s = fminf(fmaxf(s, 0.0f), 2047.0f);
    float m = s + 12582912.0f;              // 1.5*2^23 round trick
    int i = __float_as_int(m) & 0x7FF;
    float f = s - (m - 12582912.0f);        // frac in [-0.5, 0.5]
    float2 e = t[i];
    return fmaf(f, e.y, e.x);
}

// ---------------- vectorized global reductions (sm_90+) ----------------
__device__ __forceinline__ void red4(float* p, float a, float b, float c, float d) {
    asm volatile("red.global.add.v4.f32 [%0], {%1, %2, %3, %4};"
                 :: "l"(p), "f"(a), "f"(b), "f"(c), "f"(d) : "memory");
}
__device__ __forceinline__ void red2(float* p, float a, float b) {
    asm volatile("red.global.add.v2.f32 [%0], {%1, %2};"
                 :: "l"(p), "f"(a), "f"(b) : "memory");
}

__global__ void k_tab() {
    int i = blockIdx.x * blockDim.x + threadIdx.x;
    if (i <= TAB) {
        const float h = 1.0f / 128.0f;
        float xi = -8.0f + (float)i * h;
        g_tab[i] = make_float2(tanhf(xi), 0.5f * (tanhf(xi + h) - tanhf(xi - h)));
    }
}

__global__ void k_pack(const int* __restrict__ ei) {
    int i = blockIdx.x * blockDim.x + threadIdx.x;
    if (i < NE) g_ei[i] = make_int2(ei[i], ei[NE + i]);
}

// u_j = sum_k xc_k * e1w[k][j] + e1b[j]   (rows 0..9  -> x[col] side)
// v_j = sum_k xc_k * e1w[10+k][j]         (rows 10..19 -> x[row] side)
// Pack u, v, xc into one 64B fp16 row.
__device__ __forceinline__ void store_node_row(int n, const float* xc,
                                               const float* s_e1w, const float* s_e1b) {
    float u[8], v[8];
#pragma unroll
    for (int j = 0; j < 8; j++) { u[j] = s_e1b[j]; v[j] = 0.0f; }
#pragma unroll
    for (int k = 0; k < 10; k++) {
        float xk = xc[k];
        float4 a0 = *(const float4*)(s_e1w + k * 8);
        float4 a1 = *(const float4*)(s_e1w + k * 8 + 4);
        float4 b0 = *(const float4*)(s_e1w + (10 + k) * 8);
        float4 b1 = *(const float4*)(s_e1w + (10 + k) * 8 + 4);
        u[0] = fmaf(xk, a0.x, u[0]); u[1] = fmaf(xk, a0.y, u[1]);
        u[2] = fmaf(xk, a0.z, u[2]); u[3] = fmaf(xk, a0.w, u[3]);
        u[4] = fmaf(xk, a1.x, u[4]); u[5] = fmaf(xk, a1.y, u[5]);
        u[6] = fmaf(xk, a1.z, u[6]); u[7] = fmaf(xk, a1.w, u[7]);
        v[0] = fmaf(xk, b0.x, v[0]); v[1] = fmaf(xk, b0.y, v[1]);
        v[2] = fmaf(xk, b0.z, v[2]); v[3] = fmaf(xk, b0.w, v[3]);
        v[4] = fmaf(xk, b1.x, v[4]); v[5] = fmaf(xk, b1.y, v[5]);
        v[6] = fmaf(xk, b1.z, v[6]); v[7] = fmaf(xk, b1.w, v[7]);
    }
    union { __half2 h[16]; uint4 q[4]; } row;
#pragma unroll
    for (int j = 0; j < 4; j++) row.h[j]     = __float22half2_rn(make_float2(u[2*j], u[2*j+1]));
#pragma unroll
    for (int j = 0; j < 4; j++) row.h[4 + j] = __float22half2_rn(make_float2(v[2*j], v[2*j+1]));
#pragma unroll
    for (int j = 0; j < 5; j++) row.h[8 + j] = __float22half2_rn(make_float2(xc[2*j], xc[2*j+1]));
    row.h[13] = __half2(); row.h[14] = __half2(); row.h[15] = __half2();
    uint4* o = (uint4*)(g_node + (size_t)n * 32);
    o[0] = row.q[0]; o[1] = row.q[1]; o[2] = row.q[2]; o[3] = row.q[3];
}

// ---------------- init: H = tanh(X@win + b); node row; zero mimo ----------------
__global__ void k_init(const float* __restrict__ x,
                       const float* __restrict__ win_w, const float* __restrict__ win_b,
                       const float* __restrict__ e1_w, const float* __restrict__ e1_b) {
    __shared__ __align__(16) float2 s_tab[TAB];
    __shared__ __align__(16) float s_w[192];
    int tid = threadIdx.x;
    for (int i = tid; i < TAB; i += blockDim.x) s_tab[i] = g_tab[i];
    if (tid < 16) s_w[tid] = win_w[tid];
    if (tid >= 16 && tid < 24) s_w[tid] = win_b[tid - 16];
    for (int i = tid; i < 160; i += blockDim.x) s_w[24 + i] = e1_w[i];
    if (tid < 8) s_w[184 + tid] = e1_b[tid];
    __syncthreads();

    int n = blockIdx.x * blockDim.x + tid;
    if (n >= NN) return;

    float2 X = ((const float2*)x)[n];
    float xc[10];
#pragma unroll
    for (int j = 0; j < 8; j++) {
        float a = fmaf(X.x, s_w[j], fmaf(X.y, s_w[8 + j], s_w[16 + j]));
        xc[j] = tanh_lut(a, s_tab);
    }
    xc[8] = X.x; xc[9] = X.y;

    float4* mrow = (float4*)(g_mimo + (size_t)n * 32);
    float4 z4 = make_float4(0, 0, 0, 0);
#pragma unroll
    for (int q = 0; q < 8; q++) mrow[q] = z4;

    store_node_row(n, xc, s_w + 24, s_w + 184);
}

// ---------------- edge pass: e = sigmoid(w2 . tanh(u[c]+v[r]) + b2) ----------------
// iters: mi[c] += x[r]*e ; mo[r] += x[c]*e   |   final: out[i] = e
template <bool FINAL>
__global__ void k_edge(const float* __restrict__ e2_w, const float* __restrict__ e2_b,
                       float* __restrict__ out) {
    __shared__ __align__(16) float2 s_tab[TAB];
    __shared__ float s_w2[12];
    int tid = threadIdx.x;
    for (int i = tid; i < TAB; i += blockDim.x) s_tab[i] = g_tab[i];
    if (tid < 8) s_w2[tid] = e2_w[tid];
    if (tid == 8) s_w2[8] = e2_b[0];
    __syncthreads();

    float w0 = s_w2[0], w1 = s_w2[1], w2 = s_w2[2], w3 = s_w2[3];
    float w4 = s_w2[4], w5 = s_w2[5], w6 = s_w2[6], w7 = s_w2[7];
    float b2 = s_w2[8];

    int stride = gridDim.x * blockDim.x;
    for (int i = blockIdx.x * blockDim.x + tid; i < NE; i += stride) {
        int2 rc = g_ei[i];
        const __half* cb = g_node + (size_t)rc.y * 32;  // col node
        const __half* rb = g_node + (size_t)rc.x * 32;  // row node

        uint4 uq = *(const uint4*)(cb);        // u[c]  (8 halves)
        uint4 vq = *(const uint4*)(rb + 8);    // v[r]  (8 halves)
        const __half2* uh = (const __half2*)&uq;
        const __half2* vh = (const __half2*)&vq;

        float2 t0 = __half22float2(__hadd2(uh[0], vh[0]));
        float2 t1 = __half22float2(__hadd2(uh[1], vh[1]));
        float2 t2 = __half22float2(__hadd2(uh[2], vh[2]));
        float2 t3 = __half22float2(__hadd2(uh[3], vh[3]));

        float z = b2;
        z = fmaf(tanh_lut(t0.x, s_tab), w0, z);
        z = fmaf(tanh_lut(t0.y, s_tab), w1, z);
        z = fmaf(tanh_lut(t1.x, s_tab), w2, z);
        z = fmaf(tanh_lut(t1.y, s_tab), w3, z);
        z = fmaf(tanh_lut(t2.x, s_tab), w4, z);
        z = fmaf(tanh_lut(t2.y, s_tab), w5, z);
        z = fmaf(tanh_lut(t3.x, s_tab), w6, z);
        z = fmaf(tanh_lut(t3.y, s_tab), w7, z);
        float e = fmaf(tanh_lut(0.5f * z, s_tab), 0.5f, 0.5f);  // sigmoid(z)

        if (FINAL) {
            out[i] = e;
        } else {
            // gather xc of both endpoints (fp16): 16B + 4B each
            uint4 xrq = *(const uint4*)(rb + 16);
            unsigned xr89 = *(const unsigned*)(rb + 24);
            uint4 xcq = *(const uint4*)(cb + 16);
            unsigned xc89 = *(const unsigned*)(cb + 24);
            const __half2* xrh = (const __half2*)&xrq;
            const __half2* xch = (const __half2*)&xcq;

            float2 r0 = __half22float2(xrh[0]), r1 = __half22float2(xrh[1]);
            float2 r2 = __half22float2(xrh[2]), r3 = __half22float2(xrh[3]);
            float2 r4 = __half22float2(*(const __half2*)&xr89);
            float2 c0 = __half22float2(xch[0]), c1 = __half22float2(xch[1]);
            float2 c2 = __half22float2(xch[2]), c3 = __half22float2(xch[3]);
            float2 c4 = __half22float2(*(const __half2*)&xc89);

            float* mc = g_mimo + (size_t)rc.y * 32;       // mi[col]
            float* mr = g_mimo + (size_t)rc.x * 32 + 16;  // mo[row]
            red4(mc,     r0.x * e, r0.y * e, r1.x * e, r1.y * e);
            red4(mc + 4, r2.x * e, r2.y * e, r3.x * e, r3.y * e);
            red2(mc + 8, r4.x * e, r4.y * e);
            red4(mr,     c0.x * e, c0.y * e, c1.x * e, c1.y * e);
            red4(mr + 4, c2.x * e, c2.y * e, c3.x * e, c3.y * e);
            red2(mr + 8, c4.x * e, c4.y * e);
        }
    }
}

// ---------------- node pass: H = tanh(tanh([mi,mo,xcat]@n1+b1)@n2+b2) ----------------
// smem: [0:240) n1w, [240:248) n1b, [248:312) n2w, [312:320) n2b,
//       [320:480) e1w, [480:488) e1b
__global__ void k_node(const float* __restrict__ e1_w, const float* __restrict__ e1_b,
                       const float* __restrict__ n1_w, const float* __restrict__ n1_b,
                       const float* __restrict__ n2_w, const float* __restrict__ n2_b) {
    __shared__ __align__(16) float2 s_tab[TAB];
    __shared__ __align__(16) float s_w[488];
    int tid = threadIdx.x;
    for (int i = tid; i < TAB; i += blockDim.x) s_tab[i] = g_tab[i];
    for (int i = tid; i < 240; i += blockDim.x) s_w[i] = n1_w[i];
    if (tid < 8) s_w[240 + tid] = n1_b[tid];
    for (int i = tid; i < 64; i += blockDim.x) s_w[248 + i] = n2_w[i];
    if (tid < 8) s_w[312 + tid] = n2_b[tid];
    for (int i = tid; i < 160; i += blockDim.x) s_w[320 + i] = e1_w[i];
    if (tid < 8) s_w[480 + tid] = e1_b[tid];
    __syncthreads();

    int n = blockIdx.x * blockDim.x + tid;
    if (n >= NN) return;

    float4* mrow = (float4*)(g_mimo + (size_t)n * 32);
    float4 mi0 = mrow[0], mi1 = mrow[1], mi2 = mrow[2];
    float4 mo0 = mrow[4], mo1 = mrow[5], mo2 = mrow[6];

    // reset accumulators for next edge pass
    float4 z4 = make_float4(0, 0, 0, 0);
#pragma unroll
    for (int q = 0; q < 8; q++) mrow[q] = z4;

    // old xc (fp16) from node row
    const __half* nb = g_node + (size_t)n * 32;
    uint4 xq = *(const uint4*)(nb + 16);
    unsigned x89 = *(const unsigned*)(nb + 24);
    const __half2* xh = (const __half2*)&xq;
    float2 p0 = __half22float2(xh[0]), p1 = __half22float2(xh[1]);
    float2 p2 = __half22float2(xh[2]), p3 = __half22float2(xh[3]);
    float2 p4 = __half22float2(*(const __half2*)&x89);

    float M[30];
    M[0]=mi0.x; M[1]=mi0.y; M[2]=mi0.z; M[3]=mi0.w;
    M[4]=mi1.x; M[5]=mi1.y; M[6]=mi1.z; M[7]=mi1.w;
    M[8]=mi2.x; M[9]=mi2.y;
    M[10]=mo0.x; M[11]=mo0.y; M[12]=mo0.z; M[13]=mo0.w;
    M[14]=mo1.x; M[15]=mo1.y; M[16]=mo1.z; M[17]=mo1.w;
    M[18]=mo2.x; M[19]=mo2.y;
    M[20]=p0.x; M[21]=p0.y; M[22]=p1.x; M[23]=p1.y;
    M[24]=p2.x; M[25]=p2.y; M[26]=p3.x; M[27]=p3.y;
    M[28]=p4.x; M[29]=p4.y;

    float a[8];
#pragma unroll
    for (int j = 0; j < 8; j++) a[j] = s_w[240 + j];
#pragma unroll
    for (int k = 0; k < 30; k++) {
        float mk = M[k];
        float4 wA = *(const float4*)(s_w + k * 8);
        float4 wB = *(const float4*)(s_w + k * 8 + 4);
        a[0] = fmaf(mk, wA.x, a[0]); a[1] = fmaf(mk, wA.y, a[1]);
        a[2] = fmaf(mk, wA.z, a[2]); a[3] = fmaf(mk, wA.w, a[3]);
        a[4] = fmaf(mk, wB.x, a[4]); a[5] = fmaf(mk, wB.y, a[5]);
        a[6] = fmaf(mk, wB.z, a[6]); a[7] = fmaf(mk, wB.w, a[7]);
    }
    float h[8];
#pragma unroll
    for (int j = 0; j < 8; j++) h[j] = tanh_lut(a[j], s_tab);

    float g[8];
#pragma unroll
    for (int j = 0; j < 8; j++) g[j] = s_w[312 + j];
#pragma unroll
    for (int k = 0; k < 8; k++) {
        float hk = h[k];
        float4 wA = *(const float4*)(s_w + 248 + k * 8);
        float4 wB = *(const float4*)(s_w + 248 + k * 8 + 4);
        g[0] = fmaf(hk, wA.x, g[0]); g[1] = fmaf(hk, wA.y, g[1]);
        g[2] = fmaf(hk, wA.z, g[2]); g[3] = fmaf(hk, wA.w, g[3]);
        g[4] = fmaf(hk, wB.x, g[4]); g[5] = fmaf(hk, wB.y, g[5]);
        g[6] = fmaf(hk, wB.z, g[6]); g[7] = fmaf(hk, wB.w, g[7]);
    }

    float xc[10];
#pragma unroll
    for (int j = 0; j < 8; j++) xc[j] = tanh_lut(g[j], s_tab);
    xc[8] = p4.x; xc[9] = p4.y;

    store_node_row(n, xc, s_w + 320, s_w + 480);
}

extern "C" void kernel_launch(void* const* d_in, const int* in_sizes, int n_in,
                              void* d_out, int out_size) {
    const float* x     = (const float*)d_in[0];
    const int*   ei    = (const int*)d_in[1];
    const float* win_w = (const float*)d_in[2];
    const float* win_b = (const float*)d_in[3];
    const float* e1_w  = (const float*)d_in[4];
    const float* e1_b  = (const float*)d_in[5];
    const float* e2_w  = (const float*)d_in[6];
    const float* e2_b  = (const float*)d_in[7];
    const float* n1_w  = (const float*)d_in[8];
    const float* n1_b  = (const float*)d_in[9];
    const float* n2_w  = (const float*)d_in[10];
    const float* n2_b  = (const float*)d_in[11];
    float* out = (float*)d_out;

    k_tab<<<9, 256>>>();
    k_pack<<<(NE + 255) / 256, 256>>>(ei);
    k_init<<<(NN + 255) / 256, 256>>>(x, win_w, win_b, e1_w, e1_b);
    for (int it = 0; it < 3; it++) {
        k_edge<false><<<2368, 256>>>(e2_w, e2_b, nullptr);
        k_node<<<(NN + 255) / 256, 256>>>(e1_w, e1_b, n1_w, n1_b, n2_w, n2_b);
    }
    k_edge<true><<<2368, 256>>>(e2_w, e2_b, out);
}

// round 4
// speedup vs baseline: 1.8288x; 1.4585x over previous
#include <cuda_runtime.h>
#include <cuda_fp16.h>
#include <math.h>

#define NN 500000
#define NE 4000000
#define TAB 2048

// Persistent device scratch (allocation-free rule: __device__ globals).
// Edge-view row: 32 halves = 64B.  [u:0-8 | q:8-16 | v:16-24 | p:24-32]
//   col side reads u,q (bytes 0..31); row side reads v,p (bytes 32..63)
__device__ __align__(128) __half g_ev[NN * 32];   // 32MB
// Accumulator row: 16 floats = 64B. [ai:0-8 | ao:8-16]
__device__ __align__(128) float g_acc[NN * 16];   // 32MB
// xc (fp32), node-pass linear access only: 12 floats/row [xc(10), pad]
__device__ __align__(16)  float g_xc[NN * 12];    // 24MB
__device__ __align__(16)  float2 g_tab[TAB + 8];  // tanh LUT (value, central slope)
__device__ __align__(16)  int2 g_ei[NE];          // packed (row, col)  32MB

// ---------------- tanh via shared-memory lerp LUT ----------------
__device__ __forceinline__ float tanh_lut(float x, const float2* t) {
    float s = fmaf(x, 128.0f, 1024.0f);
    s = fminf(fmaxf(s, 0.0f), 2047.0f);
    float m = s + 12582912.0f;              // 1.5*2^23 round trick
    int i = __float_as_int(m) & 0x7FF;
    float f = s - (m - 12582912.0f);        // frac in [-0.5, 0.5]
    float2 e = t[i];
    return fmaf(f, e.y, e.x);
}

__device__ __forceinline__ void red4(float* p, float a, float b, float c, float d) {
    asm volatile("red.global.add.v4.f32 [%0], {%1, %2, %3, %4};"
                 :: "l"(p), "f"(a), "f"(b), "f"(c), "f"(d) : "memory");
}

__global__ void k_tab() {
    int i = blockIdx.x * blockDim.x + threadIdx.x;
    if (i <= TAB) {
        const float h = 1.0f / 128.0f;
        float xi = -8.0f + (float)i * h;
        g_tab[i] = make_float2(tanhf(xi), 0.5f * (tanhf(xi + h) - tanhf(xi - h)));
    }
}

__global__ void k_pack(const int* __restrict__ ei) {
    int i = blockIdx.x * blockDim.x + threadIdx.x;
    if (i < NE) g_ei[i] = make_int2(ei[i], ei[NE + i]);
}

// o1[j] = bias[j] + sum_k xc_k * w[k*8+j]      (rows 0..9)
// o2[j] =           sum_k xc_k * w[(10+k)*8+j] (rows 10..19)
__device__ __forceinline__ void proj2(const float* xc, const float* w,
                                      const float* bias, float* o1, float* o2) {
#pragma unroll
    for (int j = 0; j < 8; j++) { o1[j] = bias ? bias[j] : 0.0f; o2[j] = 0.0f; }
#pragma unroll
    for (int k = 0; k < 10; k++) {
        float xk = xc[k];
        float4 a0 = *(const float4*)(w + k * 8);
        float4 a1 = *(const float4*)(w + k * 8 + 4);
        float4 b0 = *(const float4*)(w + (10 + k) * 8);
        float4 b1 = *(const float4*)(w + (10 + k) * 8 + 4);
        o1[0] = fmaf(xk, a0.x, o1[0]); o1[1] = fmaf(xk, a0.y, o1[1]);
        o1[2] = fmaf(xk, a0.z, o1[2]); o1[3] = fmaf(xk, a0.w, o1[3]);
        o1[4] = fmaf(xk, a1.x, o1[4]); o1[5] = fmaf(xk, a1.y, o1[5]);
        o1[6] = fmaf(xk, a1.z, o1[6]); o1[7] = fmaf(xk, a1.w, o1[7]);
        o2[0] = fmaf(xk, b0.x, o2[0]); o2[1] = fmaf(xk, b0.y, o2[1]);
        o2[2] = fmaf(xk, b0.z, o2[2]); o2[3] = fmaf(xk, b0.w, o2[3]);
        o2[4] = fmaf(xk, b1.x, o2[4]); o2[5] = fmaf(xk, b1.y, o2[5]);
        o2[6] = fmaf(xk, b1.z, o2[6]); o2[7] = fmaf(xk, b1.w, o2[7]);
    }
}

// Compute u,v (edge MLP halves) and p,q (node-layer projections), pack 64B fp16 row.
__device__ __forceinline__ void store_ev(int n, const float* xc,
                                         const float* s_e1w, const float* s_e1b,
                                         const float* s_pw) {
    float u[8], v[8], p[8], q[8];
    proj2(xc, s_e1w, s_e1b, u, v);
    proj2(xc, s_pw, nullptr, p, q);
    union { __half2 h[16]; uint4 qd[4]; } row;
#pragma unroll
    for (int j = 0; j < 4; j++) {
        row.h[j]      = __float22half2_rn(make_float2(u[2*j], u[2*j+1]));
        row.h[4 + j]  = __float22half2_rn(make_float2(q[2*j], q[2*j+1]));
        row.h[8 + j]  = __float22half2_rn(make_float2(v[2*j], v[2*j+1]));
        row.h[12 + j] = __float22half2_rn(make_float2(p[2*j], p[2*j+1]));
    }
    uint4* o = (uint4*)(g_ev + (size_t)n * 32);
    o[0] = row.qd[0]; o[1] = row.qd[1]; o[2] = row.qd[2]; o[3] = row.qd[3];
}

// ---------------- init ----------------
// smem: [0:16) winw, [16:24) winb, [24:184) e1w, [184:192) e1b, [192:352) n1w rows 0..19
__global__ void k_init(const float* __restrict__ x,
                       const float* __restrict__ win_w, const float* __restrict__ win_b,
                       const float* __restrict__ e1_w, const float* __restrict__ e1_b,
                       const float* __restrict__ n1_w) {
    __shared__ __align__(16) float s_w[352];
    __shared__ __align__(16) float2 s_tab[TAB];
    int tid = threadIdx.x;
    for (int i = tid; i < TAB; i += blockDim.x) s_tab[i] = g_tab[i];
    if (tid < 16) s_w[tid] = win_w[tid];
    if (tid >= 16 && tid < 24) s_w[tid] = win_b[tid - 16];
    for (int i = tid; i < 160; i += blockDim.x) s_w[24 + i] = e1_w[i];
    if (tid < 8) s_w[184 + tid] = e1_b[tid];
    for (int i = tid; i < 160; i += blockDim.x) s_w[192 + i] = n1_w[i];
    __syncthreads();

    int n = blockIdx.x * blockDim.x + tid;
    if (n >= NN) return;

    float2 X = ((const float2*)x)[n];
    float xc[10];
#pragma unroll
    for (int j = 0; j < 8; j++) {
        float a = fmaf(X.x, s_w[j], fmaf(X.y, s_w[8 + j], s_w[16 + j]));
        xc[j] = tanh_lut(a, s_tab);
    }
    xc[8] = X.x; xc[9] = X.y;

    float4* arow = (float4*)(g_acc + (size_t)n * 16);
    float4 z4 = make_float4(0, 0, 0, 0);
    arow[0] = z4; arow[1] = z4; arow[2] = z4; arow[3] = z4;

    float* xrow = g_xc + (size_t)n * 12;
    *(float4*)xrow       = make_float4(xc[0], xc[1], xc[2], xc[3]);
    *(float4*)(xrow + 4) = make_float4(xc[4], xc[5], xc[6], xc[7]);
    *(float4*)(xrow + 8) = make_float4(xc[8], xc[9], 0.0f, 0.0f);

    store_ev(n, xc, s_w + 24, s_w + 184, s_w + 192);
}

// ---------------- edge pass ----------------
// e = sigmoid(w2 . tanh(u[c]+v[r]) + b2)
// iters: ai[c] += p[r]*e ; ao[r] += q[c]*e   |   final: out[i] = e
template <bool FINAL>
__global__ void k_edge(const float* __restrict__ e2_w, const float* __restrict__ e2_b,
                       float* __restrict__ out) {
    __shared__ __align__(16) float2 s_tab[TAB];
    __shared__ float s_w2[12];
    int tid = threadIdx.x;
    for (int i = tid; i < TAB; i += blockDim.x) s_tab[i] = g_tab[i];
    if (tid < 8) s_w2[tid] = e2_w[tid];
    if (tid == 8) s_w2[8] = e2_b[0];
    __syncthreads();

    float w0 = s_w2[0], w1 = s_w2[1], w2 = s_w2[2], w3 = s_w2[3];
    float w4 = s_w2[4], w5 = s_w2[5], w6 = s_w2[6], w7 = s_w2[7];
    float b2 = s_w2[8];

    int stride = gridDim.x * blockDim.x;
    for (int i = blockIdx.x * blockDim.x + tid; i < NE; i += stride) {
        int2 rc = g_ei[i];
        const __half* cb = g_ev + (size_t)rc.y * 32;  // col node: u,q
        const __half* rb = g_ev + (size_t)rc.x * 32;  // row node: v,p

        uint4 uq = *(const uint4*)(cb);        // u[c]
        uint4 vq = *(const uint4*)(rb + 16);   // v[r]
        const __half2* uh = (const __half2*)&uq;
        const __half2* vh = (const __half2*)&vq;

        float2 t0 = __half22float2(__hadd2(uh[0], vh[0]));
        float2 t1 = __half22float2(__hadd2(uh[1], vh[1]));
        float2 t2 = __half22float2(__hadd2(uh[2], vh[2]));
        float2 t3 = __half22float2(__hadd2(uh[3], vh[3]));

        float z = b2;
        z = fmaf(tanh_lut(t0.x, s_tab), w0, z);
        z = fmaf(tanh_lut(t0.y, s_tab), w1, z);
        z = fmaf(tanh_lut(t1.x, s_tab), w2, z);
        z = fmaf(tanh_lut(t1.y, s_tab), w3, z);
        z = fmaf(tanh_lut(t2.x, s_tab), w4, z);
        z = fmaf(tanh_lut(t2.y, s_tab), w5, z);
        z = fmaf(tanh_lut(t3.x, s_tab), w6, z);
        z = fmaf(tanh_lut(t3.y, s_tab), w7, z);
        float e = fmaf(tanh_lut(0.5f * z, s_tab), 0.5f, 0.5f);  // sigmoid(z)

        if (FINAL) {
            out[i] = e;
        } else {
            uint4 qq = *(const uint4*)(cb + 8);    // q[c]
            uint4 pq = *(const uint4*)(rb + 24);   // p[r]
            const __half2* qh = (const __half2*)&qq;
            const __half2* ph = (const __half2*)&pq;
            float2 p0 = __half22float2(ph[0]), p1 = __half22float2(ph[1]);
            float2 p2 = __half22float2(ph[2]), p3 = __half22float2(ph[3]);
            float2 q0 = __half22float2(qh[0]), q1 = __half22float2(qh[1]);
            float2 q2 = __half22float2(qh[2]), q3 = __half22float2(qh[3]);

            float* ac = g_acc + (size_t)rc.y * 16;      // ai[col]
            float* ar = g_acc + (size_t)rc.x * 16 + 8;  // ao[row]
            red4(ac,     p0.x * e, p0.y * e, p1.x * e, p1.y * e);
            red4(ac + 4, p2.x * e, p2.y * e, p3.x * e, p3.y * e);
            red4(ar,     q0.x * e, q0.y * e, q1.x * e, q1.y * e);
            red4(ar + 4, q2.x * e, q2.y * e, q3.x * e, q3.y * e);
        }
    }
}

// ---------------- node pass ----------------
// a = n1b + ai + ao + xc@n1w[20:30]; H = tanh(tanh(a)@n2 + b2); rebuild ev row.
// smem: [0:80) n1w rows 20..29, [80:88) n1b, [88:152) n2w, [152:160) n2b,
//       [160:320) e1w, [320:328) e1b, [328:488) n1w rows 0..19
__global__ void k_node(const float* __restrict__ e1_w, const float* __restrict__ e1_b,
                       const float* __restrict__ n1_w, const float* __restrict__ n1_b,
                       const float* __restrict__ n2_w, const float* __restrict__ n2_b) {
    __shared__ __align__(16) float s_w[488];
    __shared__ __align__(16) float2 s_tab[TAB];
    int tid = threadIdx.x;
    for (int i = tid; i < TAB; i += blockDim.x) s_tab[i] = g_tab[i];
    for (int i = tid; i < 80; i += blockDim.x) s_w[i] = n1_w[160 + i];
    if (tid < 8) s_w[80 + tid] = n1_b[tid];
    for (int i = tid; i < 64; i += blockDim.x) s_w[88 + i] = n2_w[i];
    if (tid < 8) s_w[152 + tid] = n2_b[tid];
    for (int i = tid; i < 160; i += blockDim.x) s_w[160 + i] = e1_w[i];
    if (tid < 8) s_w[320 + tid] = e1_b[tid];
    for (int i = tid; i < 160; i += blockDim.x) s_w[328 + i] = n1_w[i];
    __syncthreads();

    int n = blockIdx.x * blockDim.x + tid;
    if (n >= NN) return;

    float4* arow = (float4*)(g_acc + (size_t)n * 16);
    float4 ai0 = arow[0], ai1 = arow[1];
    float4 ao0 = arow[2], ao1 = arow[3];
    float4 z4 = make_float4(0, 0, 0, 0);
    arow[0] = z4; arow[1] = z4; arow[2] = z4; arow[3] = z4;  // reset for next pass

    float* xrow = g_xc + (size_t)n * 12;
    float4 x0 = *(float4*)xrow, x1 = *(float4*)(xrow + 4);
    float2 xX = *(float2*)(xrow + 8);
    float xc[10] = {x0.x, x0.y, x0.z, x0.w, x1.x, x1.y, x1.z, x1.w, xX.x, xX.y};

    float a[8];
    a[0] = s_w[80] + ai0.x + ao0.x; a[1] = s_w[81] + ai0.y + ao0.y;
    a[2] = s_w[82] + ai0.z + ao0.z; a[3] = s_w[83] + ai0.w + ao0.w;
    a[4] = s_w[84] + ai1.x + ao1.x; a[5] = s_w[85] + ai1.y + ao1.y;
    a[6] = s_w[86] + ai1.z + ao1.z; a[7] = s_w[87] + ai1.w + ao1.w;
#pragma unroll
    for (int k = 0; k < 10; k++) {
        float mk = xc[k];
        float4 wA = *(const float4*)(s_w + k * 8);
        float4 wB = *(const float4*)(s_w + k * 8 + 4);
        a[0] = fmaf(mk, wA.x, a[0]); a[1] = fmaf(mk, wA.y, a[1]);
        a[2] = fmaf(mk, wA.z, a[2]); a[3] = fmaf(mk, wA.w, a[3]);
        a[4] = fmaf(mk, wB.x, a[4]); a[5] = fmaf(mk, wB.y, a[5]);
        a[6] = fmaf(mk, wB.z, a[6]); a[7] = fmaf(mk, wB.w, a[7]);
    }
    float h[8];
#pragma unroll
    for (int j = 0; j < 8; j++) h[j] = tanh_lut(a[j], s_tab);

    float g[8];
#pragma unroll
    for (int j = 0; j < 8; j++) g[j] = s_w[152 + j];
#pragma unroll
    for (int k = 0; k < 8; k++) {
        float hk = h[k];
        float4 wA = *(const float4*)(s_w + 88 + k * 8);
        float4 wB = *(const float4*)(s_w + 88 + k * 8 + 4);
        g[0] = fmaf(hk, wA.x, g[0]); g[1] = fmaf(hk, wA.y, g[1]);
        g[2] = fmaf(hk, wA.z, g[2]); g[3] = fmaf(hk, wA.w, g[3]);
        g[4] = fmaf(hk, wB.x, g[4]); g[5] = fmaf(hk, wB.y, g[5]);
        g[6] = fmaf(hk, wB.z, g[6]); g[7] = fmaf(hk, wB.w, g[7]);
    }

    float nc[10];
#pragma unroll
    for (int j = 0; j < 8; j++) nc[j] = tanh_lut(g[j], s_tab);
    nc[8] = xX.x; nc[9] = xX.y;

    *(float4*)xrow       = make_float4(nc[0], nc[1], nc[2], nc[3]);
    *(float4*)(xrow + 4) = make_float4(nc[4], nc[5], nc[6], nc[7]);

    store_ev(n, nc, s_w + 160, s_w + 320, s_w + 328);
}

extern "C" void kernel_launch(void* const* d_in, const int* in_sizes, int n_in,
                              void* d_out, int out_size) {
    const float* x     = (const float*)d_in[0];
    const int*   ei    = (const int*)d_in[1];
    const float* win_w = (const float*)d_in[2];
    const float* win_b = (const float*)d_in[3];
    const float* e1_w  = (const float*)d_in[4];
    const float* e1_b  = (const float*)d_in[5];
    const float* e2_w  = (const float*)d_in[6];
    const float* e2_b  = (const float*)d_in[7];
    const float* n1_w  = (const float*)d_in[8];
    const float* n1_b  = (const float*)d_in[9];
    const float* n2_w  = (const float*)d_in[10];
    const float* n2_b  = (const float*)d_in[11];
    float* out = (float*)d_out;

    k_tab<<<9, 256>>>();
    k_pack<<<(NE + 255) / 256, 256>>>(ei);
    k_init<<<(NN + 255) / 256, 256>>>(x, win_w, win_b, e1_w, e1_b, n1_w);
    for (int it = 0; it < 3; it++) {
        k_edge<false><<<2368, 256>>>(e2_w, e2_b, nullptr);
        k_node<<<(NN + 255) / 256, 256>>>(e1_w, e1_b, n1_w, n1_b, n2_w, n2_b);
    }
    k_edge<true><<<2368, 256>>>(e2_w, e2_b, out);
}